// round 1
// baseline (speedup 1.0000x reference)
#include <cuda_runtime.h>
#include <math.h>

#define BB 2
#define TT 2048
#define DD 1024
#define NH 16
#define NKV 4
#define HD 64
#define NREP 4   // NH / NKV

// Scratch (device globals: no allocation allowed in kernel_launch)
__device__ float g_q[BB*TT*NH*HD];     // [B*T, 16, 64]
__device__ float g_k[BB*TT*NKV*HD];    // [B*T, 4, 64]
__device__ float g_v[BB*TT*NKV*HD];
__device__ float g_att[BB*TT*NH*HD];   // attention output before Wo

// ---------------------------------------------------------------------------
// Tiled fp32 GEMM: C[M,N] = A[M,K] @ W[K,N], all row-major, dims multiple of 64/16.
// BM=BN=64, BK=16, 256 threads, 4x4 microtile per thread.
// ---------------------------------------------------------------------------
__global__ void gemm64(const float* __restrict__ A, const float* __restrict__ W,
                       float* __restrict__ C, int M, int N, int K) {
    const int BM = 64, BN = 64, BK = 16;
    __shared__ float As[BK][BM];
    __shared__ float Bs[BK][BN];
    int tid = threadIdx.x;
    int m0 = blockIdx.y * BM, n0 = blockIdx.x * BN;
    int ty = tid / 16, tx = tid % 16;

    int ar = tid / 4;          // 0..63 : A tile row
    int ak = (tid % 4) * 4;    // 0,4,8,12 : A tile k offset (float4)
    int br = tid / 16;         // 0..15 : W tile row (k)
    int bc = (tid % 16) * 4;   // 0..60 : W tile col (float4)

    float acc[4][4] = {};

    for (int k0 = 0; k0 < K; k0 += BK) {
        float4 av = *(const float4*)&A[(size_t)(m0 + ar) * K + k0 + ak];
        As[ak + 0][ar] = av.x; As[ak + 1][ar] = av.y;
        As[ak + 2][ar] = av.z; As[ak + 3][ar] = av.w;
        float4 bv = *(const float4*)&W[(size_t)(k0 + br) * N + n0 + bc];
        *(float4*)&Bs[br][bc] = bv;
        __syncthreads();
        #pragma unroll
        for (int k = 0; k < BK; k++) {
            float a[4], b[4];
            *(float4*)a = *(const float4*)&As[k][ty * 4];
            *(float4*)b = *(const float4*)&Bs[k][tx * 4];
            #pragma unroll
            for (int i = 0; i < 4; i++)
                #pragma unroll
                for (int j = 0; j < 4; j++)
                    acc[i][j] = fmaf(a[i], b[j], acc[i][j]);
        }
        __syncthreads();
    }
    #pragma unroll
    for (int i = 0; i < 4; i++) {
        float4 v = make_float4(acc[i][0], acc[i][1], acc[i][2], acc[i][3]);
        *(float4*)&C[(size_t)(m0 + ty * 4 + i) * N + n0 + tx * 4] = v;
    }
}

// ---------------------------------------------------------------------------
// RoPE applied in-place to g_q and g_k.
// pair i in 0..31: freq = theta^(-i/32); angle = float(t)*freq (fp32-rounded to
// match the reference's fp32 outer product), then precise sin/cos.
// ---------------------------------------------------------------------------
__global__ void rope_kernel() {
    int total = BB * TT * (NH + NKV) * 32;
    int idx = blockIdx.x * blockDim.x + threadIdx.x;
    if (idx >= total) return;
    int pair = idx & 31;
    int rest = idx >> 5;
    int head = rest % (NH + NKV);
    int row  = rest / (NH + NKV);   // 0..B*T-1
    int t = row % TT;

    float freq = (float)pow(500000.0, -(double)pair / 32.0);
    float ang  = (float)t * freq;          // fp32 rounding, like jnp.outer
    float c = (float)cos((double)ang);
    float s = (float)sin((double)ang);

    float* p;
    if (head < NH) p = g_q + (size_t)row * NH * HD + head * HD + pair * 2;
    else           p = g_k + (size_t)row * NKV * HD + (head - NH) * HD + pair * 2;
    float x0 = p[0], x1 = p[1];
    p[0] = x0 * c - x1 * s;
    p[1] = x1 * c + x0 * s;
}

// ---------------------------------------------------------------------------
// Flash attention, causal. Grid: (qtile=T/64, B*NH). 128 threads.
// Thread pair (2q, 2q+1) owns query row q of the tile; each thread handles
// 32 of the 64 head dims. K/V tiles of 64 keys in smem; scores in smem
// [key][query] to keep everything register-light.
// ---------------------------------------------------------------------------
__global__ void attn_kernel(const float* __restrict__ Q, const float* __restrict__ Kg,
                            const float* __restrict__ Vg, float* __restrict__ O) {
    __shared__ float Ks[64][64];
    __shared__ float Vs[64][64];
    __shared__ float Ss[64][64];   // [key][query]

    int qt = blockIdx.x;           // query tile
    int bh = blockIdx.y;           // b*NH + h
    int b = bh / NH, h = bh % NH;
    int kvh = h / NREP;
    int tid = threadIdx.x;
    int qr = tid >> 1, half = tid & 1;
    int q0 = qt * 64;

    const float* qbase = Q + (size_t)b * TT * NH * HD + h * HD;
    const float* kbase = Kg + (size_t)b * TT * NKV * HD + kvh * HD;
    const float* vbase = Vg + (size_t)b * TT * NKV * HD + kvh * HD;

    float qreg[32];
    #pragma unroll
    for (int i = 0; i < 32; i++)
        qreg[i] = qbase[(size_t)(q0 + qr) * NH * HD + half * 32 + i];

    float o[32] = {};
    float m = -1e30f, l = 0.f;
    const float scale = 0.125f;    // 1/sqrt(64)

    for (int kt = 0; kt <= qt; kt++) {
        // load K/V tiles (64x64 floats each) with float4s
        #pragma unroll
        for (int it = 0; it < 8; it++) {
            int f4 = it * 128 + tid;
            int row = f4 >> 4, c4 = (f4 & 15) * 4;
            size_t g = (size_t)(kt * 64 + row) * (NKV * HD) + c4;
            *(float4*)&Ks[row][c4] = *(const float4*)&kbase[g];
            *(float4*)&Vs[row][c4] = *(const float4*)&vbase[g];
        }
        __syncthreads();

        bool diag = (kt == qt);
        for (int j = 0; j < 64; j++) {
            float p = 0.f;
            #pragma unroll
            for (int i = 0; i < 32; i++)
                p = fmaf(qreg[i], Ks[j][half * 32 + i], p);
            p += __shfl_xor_sync(0xffffffffu, p, 1);
            if (half == 0) {
                float sv = p * scale;
                if (diag && j > qr) sv = -1e9f;
                Ss[j][qr] = sv;
            }
        }
        __syncwarp();

        float tmax = -1e30f;
        for (int j = 0; j < 64; j++) tmax = fmaxf(tmax, Ss[j][qr]);
        float nm = fmaxf(m, tmax);
        float corr = __expf(m - nm);
        l *= corr;
        #pragma unroll
        for (int i = 0; i < 32; i++) o[i] *= corr;

        for (int j = 0; j < 64; j++) {
            float p = __expf(Ss[j][qr] - nm);
            l += p;
            #pragma unroll
            for (int i = 0; i < 32; i++)
                o[i] = fmaf(p, Vs[j][half * 32 + i], o[i]);
        }
        m = nm;
        __syncthreads();   // protect Ks/Vs/Ss for next tile
    }

    float inv = 1.f / l;
    size_t obase = ((size_t)b * TT + q0 + qr) * NH * HD + h * HD + half * 32;
    #pragma unroll
    for (int i = 0; i < 32; i++)
        O[obase + i] = o[i] * inv;
}

// ---------------------------------------------------------------------------
extern "C" void kernel_launch(void* const* d_in, const int* in_sizes, int n_in,
                              void* d_out, int out_size) {
    const float* x  = (const float*)d_in[0];
    // d_in[1] = mask (causal tril) — implemented analytically, not read
    const float* Wq = (const float*)d_in[2];
    const float* Wk = (const float*)d_in[3];
    const float* Wv = (const float*)d_in[4];
    const float* Wo = (const float*)d_in[5];
    float* out = (float*)d_out;

    float *qp, *kp, *vp, *ap;
    cudaGetSymbolAddress((void**)&qp, g_q);
    cudaGetSymbolAddress((void**)&kp, g_k);
    cudaGetSymbolAddress((void**)&vp, g_v);
    cudaGetSymbolAddress((void**)&ap, g_att);

    const int M = BB * TT;  // 4096

    gemm64<<<dim3(DD / 64, M / 64), 256>>>(x, Wq, qp, M, NH * HD, DD);   // Q proj
    gemm64<<<dim3(NKV * HD / 64, M / 64), 256>>>(x, Wk, kp, M, NKV * HD, DD);
    gemm64<<<dim3(NKV * HD / 64, M / 64), 256>>>(x, Wv, vp, M, NKV * HD, DD);

    int rope_total = BB * TT * (NH + NKV) * 32;
    rope_kernel<<<(rope_total + 255) / 256, 256>>>();

    attn_kernel<<<dim3(TT / 64, BB * NH), 128>>>(qp, kp, vp, ap);

    gemm64<<<dim3(DD / 64, M / 64), 256>>>(ap, Wo, out, M, DD, DD);      // out proj
}

// round 2
// speedup vs baseline: 1.8756x; 1.8756x over previous
#include <cuda_runtime.h>
#include <math.h>

#define BB 2
#define TT 2048
#define DD 1024
#define NH 16
#define NKV 4
#define HD 64
#define NREP 4   // NH / NKV

// Scratch (device globals: no allocation allowed in kernel_launch)
__device__ float g_q[BB*TT*NH*HD];       // [B*T, 16, 64] natural
__device__ float g_k[BB*TT*NKV*HD];      // [B*T, 4, 64]  natural
__device__ float g_v[BB*TT*NKV*HD];      // [B*T, 4, 64]  natural
__device__ float g_qt[BB*NH*HD*TT];      // [B][H][d][t]  (rope applied, transposed)
__device__ float g_kt[BB*NKV*HD*TT];     // [B][KVH][d][t]
__device__ float g_att[BB*TT*NH*HD];     // attention out, natural
__device__ __align__(16) float g_cos[TT*32];
__device__ __align__(16) float g_sin[TT*32];

// ---------------------------------------------------------------------------
// fp32 GEMM: C[M,N] = A[M,K] @ W[K,N], row-major. BM=BN=128, BK=8,
// 256 threads, 8x8 microtile. 64 FFMA : 4 LDS.128 per thread per k.
// ---------------------------------------------------------------------------
__global__ __launch_bounds__(256) void gemm128(const float* __restrict__ A,
                                               const float* __restrict__ W,
                                               float* __restrict__ C,
                                               int M, int N, int K) {
    const int BK = 8;
    __shared__ float As[BK][128];
    __shared__ float Bs[BK][128];
    int tid = threadIdx.x;
    int m0 = blockIdx.y * 128, n0 = blockIdx.x * 128;
    int ty = tid >> 4, tx = tid & 15;

    int am = tid >> 1;            // 0..127  A row
    int ak = (tid & 1) * 4;       // 0 or 4  A k offset
    int bk = tid >> 5;            // 0..7    W k row
    int bn = (tid & 31) * 4;      // 0..124  W col

    float acc[8][8] = {};

    for (int k0 = 0; k0 < K; k0 += BK) {
        float4 av = *(const float4*)&A[(size_t)(m0 + am) * K + k0 + ak];
        As[ak + 0][am] = av.x; As[ak + 1][am] = av.y;
        As[ak + 2][am] = av.z; As[ak + 3][am] = av.w;
        *(float4*)&Bs[bk][bn] = *(const float4*)&W[(size_t)(k0 + bk) * N + n0 + bn];
        __syncthreads();
        #pragma unroll
        for (int k = 0; k < BK; k++) {
            float a[8], b[8];
            *(float4*)&a[0] = *(const float4*)&As[k][ty * 8];
            *(float4*)&a[4] = *(const float4*)&As[k][ty * 8 + 4];
            *(float4*)&b[0] = *(const float4*)&Bs[k][tx * 8];
            *(float4*)&b[4] = *(const float4*)&Bs[k][tx * 8 + 4];
            #pragma unroll
            for (int i = 0; i < 8; i++)
                #pragma unroll
                for (int j = 0; j < 8; j++)
                    acc[i][j] = fmaf(a[i], b[j], acc[i][j]);
        }
        __syncthreads();
    }
    #pragma unroll
    for (int i = 0; i < 8; i++) {
        float* cr = &C[(size_t)(m0 + ty * 8 + i) * N + n0 + tx * 8];
        *(float4*)&cr[0] = make_float4(acc[i][0], acc[i][1], acc[i][2], acc[i][3]);
        *(float4*)&cr[4] = make_float4(acc[i][4], acc[i][5], acc[i][6], acc[i][7]);
    }
}

// ---------------------------------------------------------------------------
// RoPE cos/sin table: one entry per (t, pair). Double math, tiny grid.
// Matches reference: fp32 freq, fp32 angle (t*freq), then precise trig.
// ---------------------------------------------------------------------------
__global__ void rope_table() {
    int idx = blockIdx.x * blockDim.x + threadIdx.x;
    if (idx >= TT * 32) return;
    int t = idx >> 5, pair = idx & 31;
    float freq = (float)pow(500000.0, -(double)pair / 32.0);
    float ang = (float)t * freq;
    g_cos[idx] = (float)cos((double)ang);
    g_sin[idx] = (float)sin((double)ang);
}

// ---------------------------------------------------------------------------
// Fused RoPE + transpose: src [B][T][nheads][64] -> dst [B][nheads][64][T].
// 32x32 tiles over (t, d). Grid: (T/32, 64/32, B*nheads). 256 threads.
// ---------------------------------------------------------------------------
__global__ __launch_bounds__(256) void ropeT(const float* __restrict__ src,
                                             float* __restrict__ dst, int nheads) {
    __shared__ float Ts[32][33];
    int t0 = blockIdx.x * 32, d0 = blockIdx.y * 32;
    int bh = blockIdx.z;
    int b = bh / nheads, h = bh % nheads;
    int tid = threadIdx.x;

    int row = tid >> 3;           // t within tile, 0..31
    int c4  = (tid & 7) * 4;      // d within tile
    int t = t0 + row;
    float4 v = *(const float4*)&src[((size_t)(b * TT + t) * nheads + h) * HD + d0 + c4];
    int ci = t * 32 + (d0 + c4) / 2;
    float2 cs = *(const float2*)&g_cos[ci];
    float2 sn = *(const float2*)&g_sin[ci];
    Ts[c4 + 0][row] = v.x * cs.x - v.y * sn.x;
    Ts[c4 + 1][row] = v.y * cs.x + v.x * sn.x;
    Ts[c4 + 2][row] = v.z * cs.y - v.w * sn.y;
    Ts[c4 + 3][row] = v.w * cs.y + v.z * sn.y;
    __syncthreads();

    int dr = tid >> 3;            // d within tile
    int t4 = (tid & 7) * 4;       // t within tile
    float4 o = make_float4(Ts[dr][t4], Ts[dr][t4 + 1], Ts[dr][t4 + 2], Ts[dr][t4 + 3]);
    *(float4*)&dst[((size_t)(b * nheads + h) * HD + d0 + dr) * TT + t0 + t4] = o;
}

// ---------------------------------------------------------------------------
// Flash attention, causal. Grid: (T/64, B*NH), 256 threads.
// Q/K are d-major (transposed) so both QK^T fragments are float4 row reads.
// Each thread owns a 4x4 tile of S[64q x 64k] and of O[64q x 64d].
// Online softmax per row, replicated across the 16-lane tx group.
// ---------------------------------------------------------------------------
__global__ __launch_bounds__(256) void attn(const float* __restrict__ Qt,
                                            const float* __restrict__ Kt,
                                            const float* __restrict__ Vg,
                                            float* __restrict__ O) {
    __shared__ float Qs[64][64];   // [d][q]
    __shared__ float Ks[64][64];   // [d][k]
    __shared__ float Vs[64][64];   // [k][d]
    __shared__ float Ps[64][65];   // [k][q] (padded: transposed scalar writes)

    int qt = gridDim.x - 1 - blockIdx.x;   // long blocks first
    int bh = blockIdx.y;
    int b = bh / NH, h = bh % NH, kvh = h / NREP;
    int tid = threadIdx.x;
    int ty = tid >> 4, tx = tid & 15;
    int q0 = qt * 64;

    const float* qbase = Qt + (size_t)(b * NH + h) * HD * TT;      // [d][t]
    const float* kbase = Kt + (size_t)(b * NKV + kvh) * HD * TT;   // [d][t]
    const float* vbase = Vg + (size_t)b * TT * NKV * HD + kvh * HD;

    // Load Q tile: Qs[d][q]
    #pragma unroll
    for (int it = 0; it < 4; it++) {
        int f4 = it * 256 + tid;
        int r = f4 >> 4, c = (f4 & 15) * 4;
        *(float4*)&Qs[r][c] = *(const float4*)&qbase[(size_t)r * TT + q0 + c];
    }

    float o[4][4] = {};
    float m[4], l[4];
    #pragma unroll
    for (int i = 0; i < 4; i++) { m[i] = -1e30f; l[i] = 0.f; }
    const float scale = 0.125f;   // 1/sqrt(64)

    for (int kt = 0; kt <= qt; kt++) {
        __syncthreads();   // prior PV / Q-load visible; tiles free to overwrite
        #pragma unroll
        for (int it = 0; it < 4; it++) {
            int f4 = it * 256 + tid;
            int r = f4 >> 4, c = (f4 & 15) * 4;
            *(float4*)&Ks[r][c] = *(const float4*)&kbase[(size_t)r * TT + kt * 64 + c];
            *(float4*)&Vs[r][c] = *(const float4*)&vbase[(size_t)(kt * 64 + r) * (NKV * HD) + c];
        }
        __syncthreads();

        // S = Q^T K (both d-major)
        float s[4][4] = {};
        #pragma unroll 8
        for (int d = 0; d < 64; d++) {
            float4 a = *(const float4*)&Qs[d][ty * 4];
            float4 bk = *(const float4*)&Ks[d][tx * 4];
            float av[4] = {a.x, a.y, a.z, a.w};
            float bv[4] = {bk.x, bk.y, bk.z, bk.w};
            #pragma unroll
            for (int i = 0; i < 4; i++)
                #pragma unroll
                for (int j = 0; j < 4; j++)
                    s[i][j] = fmaf(av[i], bv[j], s[i][j]);
        }

        bool diag = (kt == qt);
        #pragma unroll
        for (int i = 0; i < 4; i++)
            #pragma unroll
            for (int j = 0; j < 4; j++) {
                s[i][j] *= scale;
                if (diag && (tx * 4 + j > ty * 4 + i)) s[i][j] = -1e9f;
            }

        // Online softmax (row stats across the 16-lane tx group)
        #pragma unroll
        for (int i = 0; i < 4; i++) {
            float rm = fmaxf(fmaxf(s[i][0], s[i][1]), fmaxf(s[i][2], s[i][3]));
            #pragma unroll
            for (int off = 8; off; off >>= 1)
                rm = fmaxf(rm, __shfl_xor_sync(0xffffffffu, rm, off));
            float nm = fmaxf(m[i], rm);
            float corr = __expf(m[i] - nm);
            l[i] *= corr;
            #pragma unroll
            for (int j = 0; j < 4; j++) o[i][j] *= corr;
            m[i] = nm;
            float rs = 0.f;
            #pragma unroll
            for (int j = 0; j < 4; j++) {
                s[i][j] = __expf(s[i][j] - nm);
                rs += s[i][j];
            }
            #pragma unroll
            for (int off = 8; off; off >>= 1)
                rs += __shfl_xor_sync(0xffffffffu, rs, off);
            l[i] += rs;
        }

        // P transposed into smem: Ps[k][q]
        #pragma unroll
        for (int i = 0; i < 4; i++)
            #pragma unroll
            for (int j = 0; j < 4; j++)
                Ps[tx * 4 + j][ty * 4 + i] = s[i][j];
        __syncthreads();

        // O += P V
        #pragma unroll 8
        for (int kk = 0; kk < 64; kk++) {
            float a[4];
            #pragma unroll
            for (int i = 0; i < 4; i++) a[i] = Ps[kk][ty * 4 + i];
            float4 bv4 = *(const float4*)&Vs[kk][tx * 4];
            float bv[4] = {bv4.x, bv4.y, bv4.z, bv4.w};
            #pragma unroll
            for (int i = 0; i < 4; i++)
                #pragma unroll
                for (int j = 0; j < 4; j++)
                    o[i][j] = fmaf(a[i], bv[j], o[i][j]);
        }
    }

    #pragma unroll
    for (int i = 0; i < 4; i++) {
        float inv = 1.f / l[i];
        float4 w = make_float4(o[i][0] * inv, o[i][1] * inv, o[i][2] * inv, o[i][3] * inv);
        *(float4*)&O[((size_t)(b * TT + q0 + ty * 4 + i)) * (NH * HD) + h * HD + tx * 4] = w;
    }
}

// ---------------------------------------------------------------------------
extern "C" void kernel_launch(void* const* d_in, const int* in_sizes, int n_in,
                              void* d_out, int out_size) {
    const float* x  = (const float*)d_in[0];
    // d_in[1] = mask (causal tril) — implemented analytically, not read
    const float* Wq = (const float*)d_in[2];
    const float* Wk = (const float*)d_in[3];
    const float* Wv = (const float*)d_in[4];
    const float* Wo = (const float*)d_in[5];
    float* out = (float*)d_out;

    float *qp, *kp, *vp, *qtp, *ktp, *ap;
    cudaGetSymbolAddress((void**)&qp, g_q);
    cudaGetSymbolAddress((void**)&kp, g_k);
    cudaGetSymbolAddress((void**)&vp, g_v);
    cudaGetSymbolAddress((void**)&qtp, g_qt);
    cudaGetSymbolAddress((void**)&ktp, g_kt);
    cudaGetSymbolAddress((void**)&ap, g_att);

    const int M = BB * TT;  // 4096

    gemm128<<<dim3(DD / 128, M / 128), 256>>>(x, Wq, qp, M, NH * HD, DD);
    gemm128<<<dim3(NKV * HD / 128, M / 128), 256>>>(x, Wk, kp, M, NKV * HD, DD);
    gemm128<<<dim3(NKV * HD / 128, M / 128), 256>>>(x, Wv, vp, M, NKV * HD, DD);

    rope_table<<<(TT * 32 + 255) / 256, 256>>>();

    ropeT<<<dim3(TT / 32, HD / 32, BB * NH), 256>>>(qp, qtp, NH);
    ropeT<<<dim3(TT / 32, HD / 32, BB * NKV), 256>>>(kp, ktp, NKV);

    attn<<<dim3(TT / 64, BB * NH), 256>>>(qtp, ktp, vp, ap);

    gemm128<<<dim3(DD / 128, M / 128), 256>>>(ap, Wo, out, M, DD, DD);
}

// round 4
// speedup vs baseline: 3.0793x; 1.6418x over previous
#include <cuda_runtime.h>
#include <cuda_bf16.h>
#include <math.h>
#include <stdint.h>

#define BB 2
#define TT 2048
#define DD 1024
#define NH 16
#define NKV 4
#define HD 64
#define NREP 4           // NH / NKV
#define MM (BB*TT)       // 4096
#define NQKV (NH*HD + 2*NKV*HD)   // 1536 fused QKV output width

// ---------------- scratch (device globals; no runtime allocation) -----------
__device__ float g_qkv[MM*NQKV];            // fused QKV proj out (fp32)
__device__ float g_qt[BB*NH*HD*TT];         // rope'd Q, [B][H][d][t]
__device__ float g_kt[BB*NKV*HD*TT];        // rope'd K, [B][KVH][d][t]
__device__ float g_att[MM*DD];              // attention out (fp32)
__device__ __align__(16) float g_cos[TT*32];
__device__ __align__(16) float g_sin[TT*32];
// bf16 hi/lo split operands
__device__ __nv_bfloat16 g_xhi[MM*DD],  g_xlo[MM*DD];
__device__ __nv_bfloat16 g_ahi[MM*DD],  g_alo[MM*DD];
__device__ __nv_bfloat16 g_wt_hi[NQKV*DD], g_wt_lo[NQKV*DD];   // fused QKV weights^T [N][K]
__device__ __nv_bfloat16 g_wot_hi[DD*DD],  g_wot_lo[DD*DD];    // Wo^T [N][K]

// ---------------- helpers ----------------------------------------------------
__device__ __forceinline__ uint32_t smem_u32(const void* p) {
    uint32_t a;
    asm("{ .reg .u64 t; cvta.to.shared.u64 t, %1; cvt.u32.u64 %0, t; }"
        : "=r"(a) : "l"(p));
    return a;
}
#define SWZ(off) ((off) ^ (((off) >> 3) & 0x70))

#define CP_ASYNC16(dst, src) \
    asm volatile("cp.async.cg.shared.global [%0], [%1], 16;" \
                 :: "r"(dst), "l"(src) : "memory")
#define CP_COMMIT() asm volatile("cp.async.commit_group;" ::: "memory")
#define CP_WAIT(n)  asm volatile("cp.async.wait_group %0;" :: "n"(n) : "memory")

#define LDSM4(r0, r1, r2, r3, addr) \
    asm volatile("ldmatrix.sync.aligned.m8n8.x4.shared.b16 {%0,%1,%2,%3}, [%4];" \
                 : "=r"(r0), "=r"(r1), "=r"(r2), "=r"(r3) : "r"(addr))

#define MMA16816(c, a, b) \
    asm volatile("mma.sync.aligned.m16n8k16.row.col.f32.bf16.bf16.f32 " \
                 "{%0,%1,%2,%3}, {%4,%5,%6,%7}, {%8,%9}, {%0,%1,%2,%3};" \
                 : "+f"((c)[0]), "+f"((c)[1]), "+f"((c)[2]), "+f"((c)[3]) \
                 : "r"((a)[0]), "r"((a)[1]), "r"((a)[2]), "r"((a)[3]), \
                   "r"((b)[0]), "r"((b)[1]))

// ---------------------------------------------------------------------------
// Split-bf16 HMMA GEMM: C[M,N] = (Ahi+Alo)[M,K] @ (Bhi+Blo)[N,K]^T  (fp32 acc)
// 128x128 CTA tile, 8 warps (2m x 4n, warp tile 64x32), BK=64,
// cp.async double-buffered smem (2 x 64KB), SW128-swizzled ldmatrix.
// ---------------------------------------------------------------------------
__global__ __launch_bounds__(256, 1) void gemm_mma(
        const __nv_bfloat16* __restrict__ Ahi, const __nv_bfloat16* __restrict__ Alo,
        const __nv_bfloat16* __restrict__ Bhi, const __nv_bfloat16* __restrict__ Blo,
        float* __restrict__ C, int M, int N, int K) {
    extern __shared__ char smem[];
    uint32_t sbase = smem_u32(smem);
    int tid = threadIdx.x, wid = tid >> 5, lid = tid & 31;
    int m0 = blockIdx.y * 128, n0 = blockIdx.x * 128;
    int wm = wid & 1, wn = wid >> 1;           // warp: m offset wm*64, n offset wn*32
    const int nch = K / 64;

    // per-thread cp.async assignment: idx = it*256+tid -> row idx>>3, 16B unit idx&7
    const int rr = tid >> 3;                    // base row (stride 32 per it)
    const int uu = tid & 7;

    float acc[4][4][4] = {};

    // -------- chunk loader (one commit group per chunk) --------
    auto load_chunk = [&](int buf, int ch) {
        int k0 = ch * 64;
        uint32_t dbase = sbase + (uint32_t)buf * 65536u;
        #pragma unroll
        for (int arr = 0; arr < 4; arr++) {
            const __nv_bfloat16* s = (arr == 0) ? Ahi : (arr == 1) ? Alo
                                    : (arr == 2) ? Bhi : Blo;
            int rb = (arr < 2) ? m0 : n0;
            uint32_t ab = dbase + (uint32_t)arr * 16384u;
            #pragma unroll
            for (int it = 0; it < 4; it++) {
                int r = it * 32 + rr;
                const __nv_bfloat16* g = s + (size_t)(rb + r) * K + k0 + uu * 8;
                uint32_t d = ab + SWZ(r * 128 + uu * 16);
                CP_ASYNC16(d, g);
            }
        }
        CP_COMMIT();
    };

    load_chunk(0, 0);
    if (nch > 1) load_chunk(1, 1);

    for (int ch = 0; ch < nch; ch++) {
        if (ch < nch - 1) { CP_WAIT(1); } else { CP_WAIT(0); }
        __syncthreads();

        uint32_t abh = sbase + (uint32_t)(ch & 1) * 65536u;
        uint32_t abl = abh + 16384u;
        uint32_t bbh = abh + 32768u;
        uint32_t bbl = abh + 49152u;

        #pragma unroll
        for (int ks = 0; ks < 4; ks++) {
            uint32_t ah[4][4], al[4][4], bh[4][2], bl[4][2];
            // A fragments: lanes 0-15 rows, lane>>4 selects k-half
            int arow = wm * 64 + (lid & 15);
            int acol = ks * 32 + (lid >> 4) * 16;
            #pragma unroll
            for (int mi = 0; mi < 4; mi++) {
                uint32_t off = SWZ((arow + mi * 16) * 128 + acol);
                LDSM4(ah[mi][0], ah[mi][1], ah[mi][2], ah[mi][3], abh + off);
                LDSM4(al[mi][0], al[mi][1], al[mi][2], al[mi][3], abl + off);
            }
            // B fragments: group g=lid>>3: (ntile g>>1, khalf g&1)
            int g = lid >> 3, w = lid & 7;
            #pragma unroll
            for (int p = 0; p < 2; p++) {
                int nrow = wn * 32 + p * 16 + (g >> 1) * 8 + w;
                int ncol = ks * 32 + (g & 1) * 16;
                uint32_t off = SWZ(nrow * 128 + ncol);
                LDSM4(bh[2*p][0], bh[2*p][1], bh[2*p+1][0], bh[2*p+1][1], bbh + off);
                LDSM4(bl[2*p][0], bl[2*p][1], bl[2*p+1][0], bl[2*p+1][1], bbl + off);
            }
            #pragma unroll
            for (int mi = 0; mi < 4; mi++)
                #pragma unroll
                for (int ni = 0; ni < 4; ni++) {
                    MMA16816(acc[mi][ni], ah[mi], bh[ni]);
                    MMA16816(acc[mi][ni], ah[mi], bl[ni]);
                    MMA16816(acc[mi][ni], al[mi], bh[ni]);
                }
        }
        __syncthreads();
        if (ch + 2 < nch) load_chunk(ch & 1, ch + 2);
    }

    // -------- epilogue: fragment -> fp32 C --------
    #pragma unroll
    for (int mi = 0; mi < 4; mi++) {
        int row = m0 + wm * 64 + mi * 16 + (lid >> 2);
        #pragma unroll
        for (int ni = 0; ni < 4; ni++) {
            int col = n0 + wn * 32 + ni * 8 + (lid & 3) * 2;
            *(float2*)&C[(size_t)row * N + col] =
                make_float2(acc[mi][ni][0], acc[mi][ni][1]);
            *(float2*)&C[(size_t)(row + 8) * N + col] =
                make_float2(acc[mi][ni][2], acc[mi][ni][3]);
        }
    }
}

// ---------------------------------------------------------------------------
// fp32 -> bf16 hi/lo split
// ---------------------------------------------------------------------------
__global__ void conv_hilo(const float* __restrict__ in,
                          __nv_bfloat16* __restrict__ hi,
                          __nv_bfloat16* __restrict__ lo, int n) {
    int i = (blockIdx.x * blockDim.x + threadIdx.x) * 4;
    if (i >= n) return;
    float4 v = *(const float4*)(in + i);
    float vv[4] = {v.x, v.y, v.z, v.w};
    #pragma unroll
    for (int j = 0; j < 4; j++) {
        __nv_bfloat16 h = __float2bfloat16(vv[j]);
        hi[i + j] = h;
        lo[i + j] = __float2bfloat16(vv[j] - __bfloat162float(h));
    }
}

// fp32 W[K][N] -> transposed bf16 hi/lo [N][K]
__global__ __launch_bounds__(256) void convT(const float* __restrict__ W,
        __nv_bfloat16* __restrict__ thi, __nv_bfloat16* __restrict__ tlo,
        int Kd, int Nd) {
    __shared__ float Ts[32][33];
    int k0 = blockIdx.y * 32, n0 = blockIdx.x * 32;
    int r = threadIdx.x >> 3, c4 = (threadIdx.x & 7) * 4;
    float4 v = *(const float4*)&W[(size_t)(k0 + r) * Nd + n0 + c4];
    Ts[r][c4] = v.x; Ts[r][c4 + 1] = v.y; Ts[r][c4 + 2] = v.z; Ts[r][c4 + 3] = v.w;
    __syncthreads();
    #pragma unroll
    for (int j = 0; j < 4; j++) {
        float x = Ts[c4 + j][r];
        __nv_bfloat16 h = __float2bfloat16(x);
        size_t o = (size_t)(n0 + r) * Kd + k0 + c4 + j;
        thi[o] = h;
        tlo[o] = __float2bfloat16(x - __bfloat162float(h));
    }
}

// ---------------------------------------------------------------------------
// RoPE table + fused RoPE-transpose (reads fused QKV buffer)
// ---------------------------------------------------------------------------
__global__ void rope_table() {
    int idx = blockIdx.x * blockDim.x + threadIdx.x;
    if (idx >= TT * 32) return;
    int t = idx >> 5, pair = idx & 31;
    float freq = (float)pow(500000.0, -(double)pair / 32.0);
    float ang = (float)t * freq;
    g_cos[idx] = (float)cos((double)ang);
    g_sin[idx] = (float)sin((double)ang);
}

__global__ __launch_bounds__(256) void ropeT(const float* __restrict__ src,
        float* __restrict__ dst, int nheads, int rowStride, int headOff) {
    __shared__ float Ts[32][33];
    int t0 = blockIdx.x * 32, d0 = blockIdx.y * 32;
    int bh = blockIdx.z;
    int b = bh / nheads, h = bh % nheads;
    int tid = threadIdx.x;

    int row = tid >> 3;
    int c4 = (tid & 7) * 4;
    int t = t0 + row;
    float4 v = *(const float4*)&src[(size_t)(b * TT + t) * rowStride + headOff
                                    + h * HD + d0 + c4];
    int ci = t * 32 + (d0 + c4) / 2;
    float2 cs = *(const float2*)&g_cos[ci];
    float2 sn = *(const float2*)&g_sin[ci];
    Ts[c4 + 0][row] = v.x * cs.x - v.y * sn.x;
    Ts[c4 + 1][row] = v.y * cs.x + v.x * sn.x;
    Ts[c4 + 2][row] = v.z * cs.y - v.w * sn.y;
    Ts[c4 + 3][row] = v.w * cs.y + v.z * sn.y;
    __syncthreads();

    int dr = tid >> 3;
    int t4 = (tid & 7) * 4;
    float4 o = make_float4(Ts[dr][t4], Ts[dr][t4 + 1], Ts[dr][t4 + 2], Ts[dr][t4 + 3]);
    *(float4*)&dst[((size_t)(b * nheads + h) * HD + d0 + dr) * TT + t0 + t4] = o;
}

// ---------------------------------------------------------------------------
// Flash attention (fp32 CUDA cores), causal. V read from fused QKV buffer.
// ---------------------------------------------------------------------------
__global__ __launch_bounds__(256) void attn(const float* __restrict__ Qt,
                                            const float* __restrict__ Kt,
                                            const float* __restrict__ QKV,
                                            float* __restrict__ O) {
    __shared__ float Qs[64][64];
    __shared__ float Ks[64][64];
    __shared__ float Vs[64][64];
    __shared__ float Ps[64][65];

    int qt = gridDim.x - 1 - blockIdx.x;
    int bh = blockIdx.y;
    int b = bh / NH, h = bh % NH, kvh = h / NREP;
    int tid = threadIdx.x;
    int ty = tid >> 4, tx = tid & 15;
    int q0 = qt * 64;

    const float* qbase = Qt + (size_t)(b * NH + h) * HD * TT;
    const float* kbase = Kt + (size_t)(b * NKV + kvh) * HD * TT;
    const float* vbase = QKV + (size_t)b * TT * NQKV + NH * HD + NKV * HD + kvh * HD;

    #pragma unroll
    for (int it = 0; it < 4; it++) {
        int f4 = it * 256 + tid;
        int r = f4 >> 4, c = (f4 & 15) * 4;
        *(float4*)&Qs[r][c] = *(const float4*)&qbase[(size_t)r * TT + q0 + c];
    }

    float o[4][4] = {};
    float m[4], l[4];
    #pragma unroll
    for (int i = 0; i < 4; i++) { m[i] = -1e30f; l[i] = 0.f; }
    const float scale = 0.125f;

    for (int kt = 0; kt <= qt; kt++) {
        __syncthreads();
        #pragma unroll
        for (int it = 0; it < 4; it++) {
            int f4 = it * 256 + tid;
            int r = f4 >> 4, c = (f4 & 15) * 4;
            *(float4*)&Ks[r][c] = *(const float4*)&kbase[(size_t)r * TT + kt * 64 + c];
            *(float4*)&Vs[r][c] = *(const float4*)&vbase[(size_t)(kt * 64 + r) * NQKV + c];
        }
        __syncthreads();

        float s[4][4] = {};
        #pragma unroll 8
        for (int d = 0; d < 64; d++) {
            float4 a = *(const float4*)&Qs[d][ty * 4];
            float4 bk = *(const float4*)&Ks[d][tx * 4];
            float av[4] = {a.x, a.y, a.z, a.w};
            float bv[4] = {bk.x, bk.y, bk.z, bk.w};
            #pragma unroll
            for (int i = 0; i < 4; i++)
                #pragma unroll
                for (int j = 0; j < 4; j++)
                    s[i][j] = fmaf(av[i], bv[j], s[i][j]);
        }

        bool diag = (kt == qt);
        #pragma unroll
        for (int i = 0; i < 4; i++)
            #pragma unroll
            for (int j = 0; j < 4; j++) {
                s[i][j] *= scale;
                if (diag && (tx * 4 + j > ty * 4 + i)) s[i][j] = -1e9f;
            }

        #pragma unroll
        for (int i = 0; i < 4; i++) {
            float rm = fmaxf(fmaxf(s[i][0], s[i][1]), fmaxf(s[i][2], s[i][3]));
            #pragma unroll
            for (int off = 8; off; off >>= 1)
                rm = fmaxf(rm, __shfl_xor_sync(0xffffffffu, rm, off));
            float nm = fmaxf(m[i], rm);
            float corr = __expf(m[i] - nm);
            l[i] *= corr;
            #pragma unroll
            for (int j = 0; j < 4; j++) o[i][j] *= corr;
            m[i] = nm;
            float rs = 0.f;
            #pragma unroll
            for (int j = 0; j < 4; j++) {
                s[i][j] = __expf(s[i][j] - nm);
                rs += s[i][j];
            }
            #pragma unroll
            for (int off = 8; off; off >>= 1)
                rs += __shfl_xor_sync(0xffffffffu, rs, off);
            l[i] += rs;
        }

        #pragma unroll
        for (int i = 0; i < 4; i++)
            #pragma unroll
            for (int j = 0; j < 4; j++)
                Ps[tx * 4 + j][ty * 4 + i] = s[i][j];
        __syncthreads();

        #pragma unroll 8
        for (int kk = 0; kk < 64; kk++) {
            float a[4];
            #pragma unroll
            for (int i = 0; i < 4; i++) a[i] = Ps[kk][ty * 4 + i];
            float4 bv4 = *(const float4*)&Vs[kk][tx * 4];
            float bv[4] = {bv4.x, bv4.y, bv4.z, bv4.w};
            #pragma unroll
            for (int i = 0; i < 4; i++)
                #pragma unroll
                for (int j = 0; j < 4; j++)
                    o[i][j] = fmaf(a[i], bv[j], o[i][j]);
        }
    }

    #pragma unroll
    for (int i = 0; i < 4; i++) {
        float inv = 1.f / l[i];
        float4 w = make_float4(o[i][0] * inv, o[i][1] * inv, o[i][2] * inv, o[i][3] * inv);
        *(float4*)&O[((size_t)(b * TT + q0 + ty * 4 + i)) * (NH * HD) + h * HD + tx * 4] = w;
    }
}

// ---------------------------------------------------------------------------
extern "C" void kernel_launch(void* const* d_in, const int* in_sizes, int n_in,
                              void* d_out, int out_size) {
    const float* x  = (const float*)d_in[0];
    // d_in[1] = causal mask — handled analytically
    const float* Wq = (const float*)d_in[2];
    const float* Wk = (const float*)d_in[3];
    const float* Wv = (const float*)d_in[4];
    const float* Wo = (const float*)d_in[5];
    float* out = (float*)d_out;

    float *qkv, *qtp, *ktp, *ap;
    __nv_bfloat16 *xhi, *xlo, *ahi, *alo, *wth, *wtl, *woh, *wol;
    cudaGetSymbolAddress((void**)&qkv, g_qkv);
    cudaGetSymbolAddress((void**)&qtp, g_qt);
    cudaGetSymbolAddress((void**)&ktp, g_kt);
    cudaGetSymbolAddress((void**)&ap,  g_att);
    cudaGetSymbolAddress((void**)&xhi, g_xhi);
    cudaGetSymbolAddress((void**)&xlo, g_xlo);
    cudaGetSymbolAddress((void**)&ahi, g_ahi);
    cudaGetSymbolAddress((void**)&alo, g_alo);
    cudaGetSymbolAddress((void**)&wth, g_wt_hi);
    cudaGetSymbolAddress((void**)&wtl, g_wt_lo);
    cudaGetSymbolAddress((void**)&woh, g_wot_hi);
    cudaGetSymbolAddress((void**)&wol, g_wot_lo);

    cudaFuncSetAttribute(gemm_mma, cudaFuncAttributeMaxDynamicSharedMemorySize, 131072);

    rope_table<<<(TT * 32 + 255) / 256, 256>>>();

    // split x, transpose+split weights (QKV fused into one [1536][1024] buffer)
    conv_hilo<<<MM * DD / 4 / 256, 256>>>(x, xhi, xlo, MM * DD);
    convT<<<dim3(DD / 32, DD / 32), 256>>>(Wq, wth, wtl, DD, DD);
    convT<<<dim3(NKV * HD / 32, DD / 32), 256>>>(Wk, wth + (size_t)NH * HD * DD,
                                                 wtl + (size_t)NH * HD * DD, DD, NKV * HD);
    convT<<<dim3(NKV * HD / 32, DD / 32), 256>>>(Wv, wth + (size_t)(NH + NKV) * HD * DD,
                                                 wtl + (size_t)(NH + NKV) * HD * DD, DD, NKV * HD);
    convT<<<dim3(DD / 32, DD / 32), 256>>>(Wo, woh, wol, DD, DD);

    // fused QKV projection: [4096,1024] @ [1024,1536]
    gemm_mma<<<dim3(NQKV / 128, MM / 128), 256, 131072>>>(xhi, xlo, wth, wtl,
                                                          qkv, MM, NQKV, DD);

    ropeT<<<dim3(TT / 32, HD / 32, BB * NH), 256>>>(qkv, qtp, NH, NQKV, 0);
    ropeT<<<dim3(TT / 32, HD / 32, BB * NKV), 256>>>(qkv, ktp, NKV, NQKV, NH * HD);

    attn<<<dim3(TT / 64, BB * NH), 256>>>(qtp, ktp, qkv, ap);

    conv_hilo<<<MM * DD / 4 / 256, 256>>>(ap, ahi, alo, MM * DD);
    gemm_mma<<<dim3(DD / 128, MM / 128), 256, 131072>>>(ahi, alo, woh, wol,
                                                        out, MM, DD, DD);
}

// round 5
// speedup vs baseline: 6.1951x; 2.0118x over previous
#include <cuda_runtime.h>
#include <cuda_bf16.h>
#include <math.h>
#include <stdint.h>

#define BB 2
#define TT 2048
#define DD 1024
#define NH 16
#define NKV 4
#define HD 64
#define NREP 4           // NH / NKV
#define MM (BB*TT)       // 4096
#define NQKV (NH*HD + 2*NKV*HD)   // 1536 fused QKV output width

// ---------------- scratch (device globals; no runtime allocation) -----------
__device__ float g_qkv[MM*NQKV];            // fused QKV proj out (fp32)
__device__ __align__(16) float g_cos[TT*32];
__device__ __align__(16) float g_sin[TT*32];
// bf16 hi/lo split operands
__device__ __nv_bfloat16 g_xhi[MM*DD],  g_xlo[MM*DD];
__device__ __nv_bfloat16 g_ahi[MM*DD],  g_alo[MM*DD];          // attention out (bf16 split)
__device__ __nv_bfloat16 g_wt_hi[NQKV*DD], g_wt_lo[NQKV*DD];   // fused QKV weights^T [N][K]
__device__ __nv_bfloat16 g_wot_hi[DD*DD],  g_wot_lo[DD*DD];    // Wo^T [N][K]
// rope'd bf16 split Q/K in [b][h][t][d]; V^T in [b][kvh][d][t]
__device__ __nv_bfloat16 g_qhi[BB*NH*TT*HD],  g_qlo[BB*NH*TT*HD];
__device__ __nv_bfloat16 g_khi[BB*NKV*TT*HD], g_klo[BB*NKV*TT*HD];
__device__ __nv_bfloat16 g_vthi[BB*NKV*HD*TT], g_vtlo[BB*NKV*HD*TT];

// ---------------- helpers ----------------------------------------------------
__device__ __forceinline__ uint32_t smem_u32(const void* p) {
    uint32_t a;
    asm("{ .reg .u64 t; cvta.to.shared.u64 t, %1; cvt.u32.u64 %0, t; }"
        : "=r"(a) : "l"(p));
    return a;
}
#define SWZ(off) ((off) ^ (((off) >> 3) & 0x70))

#define CP_ASYNC16(dst, src) \
    asm volatile("cp.async.cg.shared.global [%0], [%1], 16;" \
                 :: "r"(dst), "l"(src) : "memory")
#define CP_COMMIT() asm volatile("cp.async.commit_group;" ::: "memory")
#define CP_WAIT(n)  asm volatile("cp.async.wait_group %0;" :: "n"(n) : "memory")

#define LDSM4(r0, r1, r2, r3, addr) \
    asm volatile("ldmatrix.sync.aligned.m8n8.x4.shared.b16 {%0,%1,%2,%3}, [%4];" \
                 : "=r"(r0), "=r"(r1), "=r"(r2), "=r"(r3) : "r"(addr))

#define MMA16816(c, a, b) \
    asm volatile("mma.sync.aligned.m16n8k16.row.col.f32.bf16.bf16.f32 " \
                 "{%0,%1,%2,%3}, {%4,%5,%6,%7}, {%8,%9}, {%0,%1,%2,%3};" \
                 : "+f"((c)[0]), "+f"((c)[1]), "+f"((c)[2]), "+f"((c)[3]) \
                 : "r"((a)[0]), "r"((a)[1]), "r"((a)[2]), "r"((a)[3]), \
                   "r"((b)[0]), "r"((b)[1]))

#define MMAS(c, a, b0, b1) \
    asm volatile("mma.sync.aligned.m16n8k16.row.col.f32.bf16.bf16.f32 " \
                 "{%0,%1,%2,%3}, {%4,%5,%6,%7}, {%8,%9}, {%0,%1,%2,%3};" \
                 : "+f"((c)[0]), "+f"((c)[1]), "+f"((c)[2]), "+f"((c)[3]) \
                 : "r"((a)[0]), "r"((a)[1]), "r"((a)[2]), "r"((a)[3]), \
                   "r"(b0), "r"(b1))

__device__ __forceinline__ void split2(float x0, float x1, uint32_t& hi, uint32_t& lo) {
    __nv_bfloat16 h0 = __float2bfloat16(x0), h1 = __float2bfloat16(x1);
    float r0 = x0 - __bfloat162float(h0), r1 = x1 - __bfloat162float(h1);
    __nv_bfloat162 H; H.x = h0; H.y = h1;
    __nv_bfloat162 L = __floats2bfloat162_rn(r0, r1);
    hi = *(uint32_t*)&H; lo = *(uint32_t*)&L;
}

// ---------------------------------------------------------------------------
// Split-bf16 HMMA GEMM: C[M,N] = (Ahi+Alo)[M,K] @ (Bhi+Blo)[N,K]^T  (fp32 acc)
// 128x128 CTA tile, 8 warps (2m x 4n), BK=64, cp.async double-buffered smem.
// ---------------------------------------------------------------------------
__global__ __launch_bounds__(256, 1) void gemm_mma(
        const __nv_bfloat16* __restrict__ Ahi, const __nv_bfloat16* __restrict__ Alo,
        const __nv_bfloat16* __restrict__ Bhi, const __nv_bfloat16* __restrict__ Blo,
        float* __restrict__ C, int M, int N, int K) {
    extern __shared__ char smem[];
    uint32_t sbase = smem_u32(smem);
    int tid = threadIdx.x, wid = tid >> 5, lid = tid & 31;
    int m0 = blockIdx.y * 128, n0 = blockIdx.x * 128;
    int wm = wid & 1, wn = wid >> 1;
    const int nch = K / 64;

    const int rr = tid >> 3;
    const int uu = tid & 7;

    float acc[4][4][4] = {};

    auto load_chunk = [&](int buf, int ch) {
        int k0 = ch * 64;
        uint32_t dbase = sbase + (uint32_t)buf * 65536u;
        #pragma unroll
        for (int arr = 0; arr < 4; arr++) {
            const __nv_bfloat16* s = (arr == 0) ? Ahi : (arr == 1) ? Alo
                                    : (arr == 2) ? Bhi : Blo;
            int rb = (arr < 2) ? m0 : n0;
            uint32_t ab = dbase + (uint32_t)arr * 16384u;
            #pragma unroll
            for (int it = 0; it < 4; it++) {
                int r = it * 32 + rr;
                const __nv_bfloat16* g = s + (size_t)(rb + r) * K + k0 + uu * 8;
                uint32_t d = ab + SWZ(r * 128 + uu * 16);
                CP_ASYNC16(d, g);
            }
        }
        CP_COMMIT();
    };

    load_chunk(0, 0);
    if (nch > 1) load_chunk(1, 1);

    for (int ch = 0; ch < nch; ch++) {
        if (ch < nch - 1) { CP_WAIT(1); } else { CP_WAIT(0); }
        __syncthreads();

        uint32_t abh = sbase + (uint32_t)(ch & 1) * 65536u;
        uint32_t abl = abh + 16384u;
        uint32_t bbh = abh + 32768u;
        uint32_t bbl = abh + 49152u;

        #pragma unroll
        for (int ks = 0; ks < 4; ks++) {
            uint32_t ah[4][4], al[4][4], bh[4][2], bl[4][2];
            int arow = wm * 64 + (lid & 15);
            int acol = ks * 32 + (lid >> 4) * 16;
            #pragma unroll
            for (int mi = 0; mi < 4; mi++) {
                uint32_t off = SWZ((arow + mi * 16) * 128 + acol);
                LDSM4(ah[mi][0], ah[mi][1], ah[mi][2], ah[mi][3], abh + off);
                LDSM4(al[mi][0], al[mi][1], al[mi][2], al[mi][3], abl + off);
            }
            int g = lid >> 3, w = lid & 7;
            #pragma unroll
            for (int p = 0; p < 2; p++) {
                int nrow = wn * 32 + p * 16 + (g >> 1) * 8 + w;
                int ncol = ks * 32 + (g & 1) * 16;
                uint32_t off = SWZ(nrow * 128 + ncol);
                LDSM4(bh[2*p][0], bh[2*p][1], bh[2*p+1][0], bh[2*p+1][1], bbh + off);
                LDSM4(bl[2*p][0], bl[2*p][1], bl[2*p+1][0], bl[2*p+1][1], bbl + off);
            }
            #pragma unroll
            for (int mi = 0; mi < 4; mi++)
                #pragma unroll
                for (int ni = 0; ni < 4; ni++) {
                    MMA16816(acc[mi][ni], ah[mi], bh[ni]);
                    MMA16816(acc[mi][ni], ah[mi], bl[ni]);
                    MMA16816(acc[mi][ni], al[mi], bh[ni]);
                }
        }
        __syncthreads();
        if (ch + 2 < nch) load_chunk(ch & 1, ch + 2);
    }

    #pragma unroll
    for (int mi = 0; mi < 4; mi++) {
        int row = m0 + wm * 64 + mi * 16 + (lid >> 2);
        #pragma unroll
        for (int ni = 0; ni < 4; ni++) {
            int col = n0 + wn * 32 + ni * 8 + (lid & 3) * 2;
            *(float2*)&C[(size_t)row * N + col] =
                make_float2(acc[mi][ni][0], acc[mi][ni][1]);
            *(float2*)&C[(size_t)(row + 8) * N + col] =
                make_float2(acc[mi][ni][2], acc[mi][ni][3]);
        }
    }
}

// ---------------------------------------------------------------------------
// HMMA flash attention, causal. Grid (T/128 reversed, B*NH), 256 threads.
// Q regs (A-frags), K/Vt chunks of 64 keys double-buffered via cp.async.
// All operands bf16 hi/lo split, fp32 accum, online softmax in registers.
// Writes bf16 hi/lo attention output directly.
// ---------------------------------------------------------------------------
__global__ __launch_bounds__(256, 1) void attn_mma(
        const __nv_bfloat16* __restrict__ Qhi, const __nv_bfloat16* __restrict__ Qlo,
        const __nv_bfloat16* __restrict__ Khi, const __nv_bfloat16* __restrict__ Klo,
        const __nv_bfloat16* __restrict__ Vthi, const __nv_bfloat16* __restrict__ Vtlo,
        __nv_bfloat16* __restrict__ Ohi, __nv_bfloat16* __restrict__ Olo) {
    extern __shared__ char smem[];
    uint32_t sbase = smem_u32(smem);
    const uint32_t QHI = 0, QLO = 16384, BUF = 32768;   // buf b at BUF + b*32768

    int tid = threadIdx.x, wid = tid >> 5, lid = tid & 31;
    int qt = gridDim.x - 1 - blockIdx.x;     // long blocks first
    int bh = blockIdx.y;
    int b = bh / NH, h = bh % NH, kvh = h / NREP;
    int q0 = qt * 128;

    const __nv_bfloat16* qbh = Qhi + (size_t)(b * NH + h) * TT * HD;
    const __nv_bfloat16* qbl = Qlo + (size_t)(b * NH + h) * TT * HD;
    const __nv_bfloat16* kbh = Khi + (size_t)(b * NKV + kvh) * TT * HD;
    const __nv_bfloat16* kbl = Klo + (size_t)(b * NKV + kvh) * TT * HD;
    const __nv_bfloat16* vbh = Vthi + (size_t)(b * NKV + kvh) * HD * TT;
    const __nv_bfloat16* vbl = Vtlo + (size_t)(b * NKV + kvh) * HD * TT;

    // ---- stage Q (group 0) ----
    {
        #pragma unroll
        for (int arr = 0; arr < 2; arr++) {
            const __nv_bfloat16* s = arr ? qbl : qbh;
            uint32_t ab = sbase + (arr ? QLO : QHI);
            #pragma unroll
            for (int it = 0; it < 4; it++) {
                int idx = it * 256 + tid;
                int r = idx >> 3, u = idx & 7;
                CP_ASYNC16(ab + SWZ(r * 128 + u * 16),
                           s + (size_t)(q0 + r) * HD + u * 8);
            }
        }
        CP_COMMIT();
    }

    auto load_chunk = [&](int buf, int kt) {
        uint32_t db = sbase + BUF + (uint32_t)buf * 32768u;
        #pragma unroll
        for (int arr = 0; arr < 4; arr++) {
            uint32_t ab = db + (uint32_t)arr * 8192u;
            #pragma unroll
            for (int it = 0; it < 2; it++) {
                int idx = it * 256 + tid;
                int r = idx >> 3, u = idx & 7;
                const __nv_bfloat16* src;
                if (arr == 0)      src = kbh + (size_t)(kt * 64 + r) * HD + u * 8;
                else if (arr == 1) src = kbl + (size_t)(kt * 64 + r) * HD + u * 8;
                else if (arr == 2) src = vbh + (size_t)r * TT + kt * 64 + u * 8;
                else               src = vbl + (size_t)r * TT + kt * 64 + u * 8;
                CP_ASYNC16(ab + SWZ(r * 128 + u * 16), src);
            }
        }
        CP_COMMIT();
    };

    int nch = 2 * qt + 2;
    load_chunk(0, 0);
    load_chunk(1, 1);

    // Q fragments to registers
    CP_WAIT(2);
    __syncthreads();
    uint32_t qfh[4][4], qfl[4][4];
    {
        int arow = wid * 16 + (lid & 15);
        #pragma unroll
        for (int ks = 0; ks < 4; ks++) {
            uint32_t off = SWZ(arow * 128 + ks * 32 + (lid >> 4) * 16);
            LDSM4(qfh[ks][0], qfh[ks][1], qfh[ks][2], qfh[ks][3], sbase + QHI + off);
            LDSM4(qfl[ks][0], qfl[ks][1], qfl[ks][2], qfl[ks][3], sbase + QLO + off);
        }
    }

    float oacc[8][4] = {};
    float mA = -1e30f, mB = -1e30f, lA = 0.f, lB = 0.f;
    const int g = lid >> 3, w8 = lid & 7;
    const int qrA = q0 + wid * 16 + (lid >> 2);

    for (int ch = 0; ch < nch; ch++) {
        if (ch < nch - 1) { CP_WAIT(1); } else { CP_WAIT(0); }
        __syncthreads();
        int kt = ch;
        bool active = (kt * 64 <= q0 + wid * 16 + 15);
        if (active) {
            uint32_t kb = sbase + BUF + (uint32_t)(ch & 1) * 32768u;
            uint32_t vb = kb + 16384u;

            // ---- S = Q K^T (3-term split) ----
            float sacc[8][4] = {};
            #pragma unroll
            for (int ks = 0; ks < 4; ks++) {
                #pragma unroll
                for (int p = 0; p < 4; p++) {
                    int nrow = p * 16 + (g >> 1) * 8 + w8;
                    uint32_t off = SWZ(nrow * 128 + ks * 32 + (g & 1) * 16);
                    uint32_t b0, b1, b2, b3, c0, c1, c2, c3;
                    LDSM4(b0, b1, b2, b3, kb + off);
                    LDSM4(c0, c1, c2, c3, kb + 8192u + off);
                    MMAS(sacc[2*p],   qfh[ks], b0, b1);
                    MMAS(sacc[2*p+1], qfh[ks], b2, b3);
                    MMAS(sacc[2*p],   qfh[ks], c0, c1);
                    MMAS(sacc[2*p+1], qfh[ks], c2, c3);
                    MMAS(sacc[2*p],   qfl[ks], b0, b1);
                    MMAS(sacc[2*p+1], qfl[ks], b2, b3);
                }
            }

            // ---- scale + causal mask ----
            #pragma unroll
            for (int nt = 0; nt < 8; nt++) {
                int kc = kt * 64 + nt * 8 + (lid & 3) * 2;
                #pragma unroll
                for (int j = 0; j < 4; j++) sacc[nt][j] *= 0.125f;
                if (kc > qrA)         sacc[nt][0] = -1e9f;
                if (kc + 1 > qrA)     sacc[nt][1] = -1e9f;
                if (kc > qrA + 8)     sacc[nt][2] = -1e9f;
                if (kc + 1 > qrA + 8) sacc[nt][3] = -1e9f;
            }

            // ---- online softmax (rows shared by 4-lane groups) ----
            float rmA = -1e30f, rmB = -1e30f;
            #pragma unroll
            for (int nt = 0; nt < 8; nt++) {
                rmA = fmaxf(rmA, fmaxf(sacc[nt][0], sacc[nt][1]));
                rmB = fmaxf(rmB, fmaxf(sacc[nt][2], sacc[nt][3]));
            }
            rmA = fmaxf(rmA, __shfl_xor_sync(0xffffffffu, rmA, 1));
            rmA = fmaxf(rmA, __shfl_xor_sync(0xffffffffu, rmA, 2));
            rmB = fmaxf(rmB, __shfl_xor_sync(0xffffffffu, rmB, 1));
            rmB = fmaxf(rmB, __shfl_xor_sync(0xffffffffu, rmB, 2));
            float mnA = fmaxf(mA, rmA), mnB = fmaxf(mB, rmB);
            float corrA = __expf(mA - mnA), corrB = __expf(mB - mnB);
            mA = mnA; mB = mnB;
            float rsA = 0.f, rsB = 0.f;
            #pragma unroll
            for (int nt = 0; nt < 8; nt++) {
                sacc[nt][0] = __expf(sacc[nt][0] - mA);
                sacc[nt][1] = __expf(sacc[nt][1] - mA);
                sacc[nt][2] = __expf(sacc[nt][2] - mB);
                sacc[nt][3] = __expf(sacc[nt][3] - mB);
                rsA += sacc[nt][0] + sacc[nt][1];
                rsB += sacc[nt][2] + sacc[nt][3];
            }
            rsA += __shfl_xor_sync(0xffffffffu, rsA, 1);
            rsA += __shfl_xor_sync(0xffffffffu, rsA, 2);
            rsB += __shfl_xor_sync(0xffffffffu, rsB, 1);
            rsB += __shfl_xor_sync(0xffffffffu, rsB, 2);
            lA = lA * corrA + rsA;
            lB = lB * corrB + rsB;
            #pragma unroll
            for (int nt = 0; nt < 8; nt++) {
                oacc[nt][0] *= corrA; oacc[nt][1] *= corrA;
                oacc[nt][2] *= corrB; oacc[nt][3] *= corrB;
            }

            // ---- O += P V (P frags from S accs, 3-term split) ----
            #pragma unroll
            for (int k2 = 0; k2 < 4; k2++) {
                uint32_t pah[4], pal[4];
                split2(sacc[2*k2][0],   sacc[2*k2][1],   pah[0], pal[0]);
                split2(sacc[2*k2][2],   sacc[2*k2][3],   pah[1], pal[1]);
                split2(sacc[2*k2+1][0], sacc[2*k2+1][1], pah[2], pal[2]);
                split2(sacc[2*k2+1][2], sacc[2*k2+1][3], pah[3], pal[3]);
                #pragma unroll
                for (int p = 0; p < 4; p++) {
                    int nrow = p * 16 + (g >> 1) * 8 + w8;
                    uint32_t off = SWZ(nrow * 128 + k2 * 32 + (g & 1) * 16);
                    uint32_t b0, b1, b2, b3, c0, c1, c2, c3;
                    LDSM4(b0, b1, b2, b3, vb + off);
                    LDSM4(c0, c1, c2, c3, vb + 8192u + off);
                    MMAS(oacc[2*p],   pah, b0, b1);
                    MMAS(oacc[2*p+1], pah, b2, b3);
                    MMAS(oacc[2*p],   pah, c0, c1);
                    MMAS(oacc[2*p+1], pah, c2, c3);
                    MMAS(oacc[2*p],   pal, b0, b1);
                    MMAS(oacc[2*p+1], pal, b2, b3);
                }
            }
        }
        __syncthreads();
        if (ch + 2 < nch) load_chunk(ch & 1, ch + 2);
    }

    // ---- epilogue: normalize, split to bf16 hi/lo, store ----
    float invA = 1.f / lA, invB = 1.f / lB;
    size_t rowA = (size_t)(b * TT + qrA);
    size_t rowB = rowA + 8;
    int colb = h * HD + (lid & 3) * 2;
    #pragma unroll
    for (int nt = 0; nt < 8; nt++) {
        uint32_t hi, lo;
        split2(oacc[nt][0] * invA, oacc[nt][1] * invA, hi, lo);
        *(uint32_t*)&Ohi[rowA * DD + colb + nt * 8] = hi;
        *(uint32_t*)&Olo[rowA * DD + colb + nt * 8] = lo;
        split2(oacc[nt][2] * invB, oacc[nt][3] * invB, hi, lo);
        *(uint32_t*)&Ohi[rowB * DD + colb + nt * 8] = hi;
        *(uint32_t*)&Olo[rowB * DD + colb + nt * 8] = lo;
    }
}

// ---------------------------------------------------------------------------
// fp32 -> bf16 hi/lo split
// ---------------------------------------------------------------------------
__global__ void conv_hilo(const float* __restrict__ in,
                          __nv_bfloat16* __restrict__ hi,
                          __nv_bfloat16* __restrict__ lo, int n) {
    int i = (blockIdx.x * blockDim.x + threadIdx.x) * 4;
    if (i >= n) return;
    float4 v = *(const float4*)(in + i);
    float vv[4] = {v.x, v.y, v.z, v.w};
    #pragma unroll
    for (int j = 0; j < 4; j++) {
        __nv_bfloat16 h = __float2bfloat16(vv[j]);
        hi[i + j] = h;
        lo[i + j] = __float2bfloat16(vv[j] - __bfloat162float(h));
    }
}

// fp32 W[K][N] -> transposed bf16 hi/lo [N][K]
__global__ __launch_bounds__(256) void convT(const float* __restrict__ W,
        __nv_bfloat16* __restrict__ thi, __nv_bfloat16* __restrict__ tlo,
        int Kd, int Nd) {
    __shared__ float Ts[32][33];
    int k0 = blockIdx.y * 32, n0 = blockIdx.x * 32;
    int r = threadIdx.x >> 3, c4 = (threadIdx.x & 7) * 4;
    float4 v = *(const float4*)&W[(size_t)(k0 + r) * Nd + n0 + c4];
    Ts[r][c4] = v.x; Ts[r][c4 + 1] = v.y; Ts[r][c4 + 2] = v.z; Ts[r][c4 + 3] = v.w;
    __syncthreads();
    #pragma unroll
    for (int j = 0; j < 4; j++) {
        float x = Ts[c4 + j][r];
        __nv_bfloat16 h = __float2bfloat16(x);
        size_t o = (size_t)(n0 + r) * Kd + k0 + c4 + j;
        thi[o] = h;
        tlo[o] = __float2bfloat16(x - __bfloat162float(h));
    }
}

// ---------------------------------------------------------------------------
// RoPE table, RoPE+split (Q/K, [b][h][t][d] bf16 hi/lo), V transpose+split
// ---------------------------------------------------------------------------
__global__ void rope_table() {
    int idx = blockIdx.x * blockDim.x + threadIdx.x;
    if (idx >= TT * 32) return;
    int t = idx >> 5, pair = idx & 31;
    float freq = (float)pow(500000.0, -(double)pair / 32.0);
    float ang = (float)t * freq;
    g_cos[idx] = (float)cos((double)ang);
    g_sin[idx] = (float)sin((double)ang);
}

__global__ void rope_split(const float* __restrict__ qkv,
        __nv_bfloat16* __restrict__ hi, __nv_bfloat16* __restrict__ lo,
        int nheads, int off) {
    int u = blockIdx.x * blockDim.x + threadIdx.x;   // BB*nheads*TT*16
    int d4 = (u & 15) * 4;
    int t = (u >> 4) % TT;
    int hh = ((u >> 4) / TT) % nheads;
    int b = u / (16 * TT * nheads);
    float4 v = *(const float4*)&qkv[(size_t)(b * TT + t) * NQKV + off + hh * HD + d4];
    int ci = t * 32 + d4 / 2;
    float2 cs = *(const float2*)&g_cos[ci];
    float2 sn = *(const float2*)&g_sin[ci];
    float r[4];
    r[0] = v.x * cs.x - v.y * sn.x;
    r[1] = v.y * cs.x + v.x * sn.x;
    r[2] = v.z * cs.y - v.w * sn.y;
    r[3] = v.w * cs.y + v.z * sn.y;
    size_t o = ((size_t)(b * nheads + hh) * TT + t) * HD + d4;
    #pragma unroll
    for (int j = 0; j < 4; j++) {
        __nv_bfloat16 hv = __float2bfloat16(r[j]);
        hi[o + j] = hv;
        lo[o + j] = __float2bfloat16(r[j] - __bfloat162float(hv));
    }
}

__global__ __launch_bounds__(256) void vT_split(const float* __restrict__ qkv) {
    __shared__ float Ts[32][33];
    int t0 = blockIdx.x * 32, d0 = blockIdx.y * 32;
    int bk = blockIdx.z;
    int b = bk / NKV, kv = bk % NKV;
    int r = threadIdx.x >> 3, c4 = (threadIdx.x & 7) * 4;
    float4 v = *(const float4*)&qkv[(size_t)(b * TT + t0 + r) * NQKV
                                    + NH * HD + NKV * HD + kv * HD + d0 + c4];
    Ts[r][c4] = v.x; Ts[r][c4 + 1] = v.y; Ts[r][c4 + 2] = v.z; Ts[r][c4 + 3] = v.w;
    __syncthreads();
    int dr = threadIdx.x >> 3, t4 = (threadIdx.x & 7) * 4;
    size_t o = ((size_t)(b * NKV + kv) * HD + d0 + dr) * TT + t0 + t4;
    #pragma unroll
    for (int j = 0; j < 4; j++) {
        float x = Ts[t4 + j][dr];
        __nv_bfloat16 h = __float2bfloat16(x);
        g_vthi[o + j] = h;
        g_vtlo[o + j] = __float2bfloat16(x - __bfloat162float(h));
    }
}

// ---------------------------------------------------------------------------
extern "C" void kernel_launch(void* const* d_in, const int* in_sizes, int n_in,
                              void* d_out, int out_size) {
    const float* x  = (const float*)d_in[0];
    // d_in[1] = causal mask — handled analytically
    const float* Wq = (const float*)d_in[2];
    const float* Wk = (const float*)d_in[3];
    const float* Wv = (const float*)d_in[4];
    const float* Wo = (const float*)d_in[5];
    float* out = (float*)d_out;

    float *qkv;
    __nv_bfloat16 *xhi, *xlo, *ahi, *alo, *wth, *wtl, *woh, *wol;
    __nv_bfloat16 *qhi, *qlo, *khi, *klo, *vthi, *vtlo;
    cudaGetSymbolAddress((void**)&qkv, g_qkv);
    cudaGetSymbolAddress((void**)&xhi, g_xhi);
    cudaGetSymbolAddress((void**)&xlo, g_xlo);
    cudaGetSymbolAddress((void**)&ahi, g_ahi);
    cudaGetSymbolAddress((void**)&alo, g_alo);
    cudaGetSymbolAddress((void**)&wth, g_wt_hi);
    cudaGetSymbolAddress((void**)&wtl, g_wt_lo);
    cudaGetSymbolAddress((void**)&woh, g_wot_hi);
    cudaGetSymbolAddress((void**)&wol, g_wot_lo);
    cudaGetSymbolAddress((void**)&qhi, g_qhi);
    cudaGetSymbolAddress((void**)&qlo, g_qlo);
    cudaGetSymbolAddress((void**)&khi, g_khi);
    cudaGetSymbolAddress((void**)&klo, g_klo);
    cudaGetSymbolAddress((void**)&vthi, g_vthi);
    cudaGetSymbolAddress((void**)&vtlo, g_vtlo);

    cudaFuncSetAttribute(gemm_mma, cudaFuncAttributeMaxDynamicSharedMemorySize, 131072);
    cudaFuncSetAttribute(attn_mma, cudaFuncAttributeMaxDynamicSharedMemorySize, 98304);

    rope_table<<<(TT * 32 + 255) / 256, 256>>>();

    conv_hilo<<<MM * DD / 4 / 256, 256>>>(x, xhi, xlo, MM * DD);
    convT<<<dim3(DD / 32, DD / 32), 256>>>(Wq, wth, wtl, DD, DD);
    convT<<<dim3(NKV * HD / 32, DD / 32), 256>>>(Wk, wth + (size_t)NH * HD * DD,
                                                 wtl + (size_t)NH * HD * DD, DD, NKV * HD);
    convT<<<dim3(NKV * HD / 32, DD / 32), 256>>>(Wv, wth + (size_t)(NH + NKV) * HD * DD,
                                                 wtl + (size_t)(NH + NKV) * HD * DD, DD, NKV * HD);
    convT<<<dim3(DD / 32, DD / 32), 256>>>(Wo, woh, wol, DD, DD);

    // fused QKV projection: [4096,1024] @ [1024,1536]
    gemm_mma<<<dim3(NQKV / 128, MM / 128), 256, 131072>>>(xhi, xlo, wth, wtl,
                                                          qkv, MM, NQKV, DD);

    rope_split<<<BB * NH * TT * 16 / 256, 256>>>(qkv, qhi, qlo, NH, 0);
    rope_split<<<BB * NKV * TT * 16 / 256, 256>>>(qkv, khi, klo, NKV, NH * HD);
    vT_split<<<dim3(TT / 32, HD / 32, BB * NKV), 256>>>(qkv);

    attn_mma<<<dim3(TT / 128, BB * NH), 256, 98304>>>(qhi, qlo, khi, klo,
                                                      vthi, vtlo, ahi, alo);

    gemm_mma<<<dim3(DD / 128, MM / 128), 256, 131072>>>(ahi, alo, woh, wol,
                                                        out, MM, DD, DD);
}